// round 1
// baseline (speedup 1.0000x reference)
#include <cuda_runtime.h>
#include <cstdint>

#define N_DIM 4
#define T_DIM 12
#define V_DIM 200
#define F_DIM 64
#define VT    50      // v-rows per block in compute kernel (== V/N, one n' band)

// ---------------------------------------------------------------------------
// Packed fp32x2 helpers (Blackwell sm_100+)
// ---------------------------------------------------------------------------
__device__ __forceinline__ unsigned long long padd2(unsigned long long a,
                                                    unsigned long long b) {
    unsigned long long r;
    asm("add.rn.f32x2 %0, %1, %2;" : "=l"(r) : "l"(a), "l"(b));
    return r;
}

__device__ __forceinline__ float2 unpack2(unsigned long long v) {
    float2 r;
    asm("mov.b64 {%0, %1}, %2;" : "=f"(r.x), "=f"(r.y) : "l"(v));
    return r;
}

// ---------------------------------------------------------------------------
// Kernel 1: compute s, exp, and scatter through the view-permutation.
//
// grid  = (4, 48): blockIdx.x = n' (the 50-row v band), blockIdx.y = n*T + t
// block = 256 threads; threads 0..199 each own one w column.
//
// Smem: y[200][64] with y = x[n,t] * a  (a >= 0 makes |dx|*a == |dy|).
// Each thread keeps -y_w (64 floats as 32 packed pairs) in registers and
// loops over 50 v rows via broadcast LDS. Inner body per 2 elements:
//   1x add.f32x2 (diff), 1x and.b64 (abs, ALU pipe), 1x add.f32x2 (acc).
// ---------------------------------------------------------------------------
extern __shared__ unsigned char smem_raw[];

__global__ void __launch_bounds__(256)
k_compute(const float* __restrict__ x, const float* __restrict__ a,
          float* __restrict__ out) {
    const int np  = blockIdx.x;          // n'  (0..3)
    const int nt  = blockIdx.y;          // n*T + t  (0..47)
    const int n   = nt / T_DIM;
    const int t   = nt % T_DIM;
    const int tid = threadIdx.x;

    float4* ys4 = reinterpret_cast<float4*>(smem_raw);           // 200*16 float4
    const float4* x4 = reinterpret_cast<const float4*>(
        x + (size_t)nt * V_DIM * F_DIM);
    const float4* a4 = reinterpret_cast<const float4*>(a);

    // Load + pre-scale slab: y[r][f] = x[nt][r][f] * a[f]
    for (int i = tid; i < V_DIM * (F_DIM / 4); i += 256) {
        const int fq = i & 15;           // F/4 == 16
        float4 v = x4[i];
        const float4 s = __ldg(&a4[fq]);
        v.x *= s.x; v.y *= s.y; v.z *= s.z; v.w *= s.w;
        ys4[i] = v;
    }
    __syncthreads();

    if (tid >= V_DIM) return;
    const int w = tid;

    const ulonglong2* ys2 = reinterpret_cast<const ulonglong2*>(smem_raw);

    // Register-resident negated w-row: 32 packed fp32 pairs.
    unsigned long long ywn[32];
    const unsigned long long NEG2 = 0x8000000080000000ULL;
    #pragma unroll
    for (int fq = 0; fq < 16; fq++) {
        ulonglong2 r = ys2[w * 16 + fq];
        ywn[2 * fq]     = r.x ^ NEG2;
        ywn[2 * fq + 1] = r.y ^ NEG2;
    }

    const unsigned long long ABS2 = 0x7FFFFFFF7FFFFFFFULL;
    // out index: ((n'*T + t)*V + v')*V + w   with v' = v*4 + n (v local in band)
    float* outp = out + ((size_t)(np * T_DIM + t) * V_DIM) * V_DIM + w;
    const int vbase = np * VT;

    for (int v = 0; v < VT; v++) {
        const ulonglong2* yv2 = ys2 + (size_t)(vbase + v) * 16;
        unsigned long long accA = 0ULL, accB = 0ULL;   // (0.f,0.f) packed
        #pragma unroll
        for (int fq = 0; fq < 16; fq++) {
            ulonglong2 q = yv2[fq];                    // broadcast LDS.128
            unsigned long long d0 = padd2(q.x, ywn[2 * fq]);
            unsigned long long d1 = padd2(q.y, ywn[2 * fq + 1]);
            d0 &= ABS2;
            d1 &= ABS2;
            accA = padd2(accA, d0);
            accB = padd2(accB, d1);
        }
        const float2 pa = unpack2(accA);
        const float2 pb = unpack2(accB);
        const float s = (pa.x + pa.y) + (pb.x + pb.y);
        outp[(size_t)(v * 4 + n) * V_DIM] = __expf(s);
    }
}

// ---------------------------------------------------------------------------
// Kernel 2: normalize over axis 2 (v') of out[N,T,V,V].
//
// grid = (48, 4): blockIdx.x = n*T+t block (flat over first two dims),
//                 blockIdx.y = w chunk of 50.
// block = 256 threads, 250 active: tid -> (vg in 0..4, wl in 0..49).
// Each vg sums 40 v' rows for its column; smem-reduce 5 partials; then
// every thread rescales its 40 rows by 1/sum.
// ---------------------------------------------------------------------------
__global__ void __launch_bounds__(256)
k_norm(float* __restrict__ out) {
    __shared__ float part[5 * 50];
    __shared__ float sinv[50];

    const int tid = threadIdx.x;
    if (tid >= 250) return;  // no syncthreads divergence issue: see barriers below

    const int vg = tid / 50;              // 0..4
    const int wl = tid % 50;              // 0..49
    const int w  = blockIdx.y * 50 + wl;  // 0..199
    float* base = out + (size_t)blockIdx.x * V_DIM * V_DIM + w;

    float p = 0.0f;
    #pragma unroll 8
    for (int i = 0; i < 40; i++)
        p += base[(size_t)(vg * 40 + i) * V_DIM];
    part[vg * 50 + wl] = p;
    __syncthreads();

    if (vg == 0) {
        const float s = part[wl] + part[50 + wl] + part[100 + wl] +
                        part[150 + wl] + part[200 + wl];
        sinv[wl] = 1.0f / s;
    }
    __syncthreads();

    const float inv = sinv[wl];
    #pragma unroll 8
    for (int i = 0; i < 40; i++) {
        float* p2 = base + (size_t)(vg * 40 + i) * V_DIM;
        *p2 = (*p2) * inv;
    }
}

// ---------------------------------------------------------------------------
// NOTE on k_norm early-return + __syncthreads: threads 250..255 exit before
// any barrier. On sm_90+ __syncthreads only waits for non-exited threads,
// so this is safe; to be conservative we size the block at 256 anyway for
// scheduling and rely on that semantic (exited threads don't participate).
// ---------------------------------------------------------------------------

extern "C" void kernel_launch(void* const* d_in, const int* in_sizes, int n_in,
                              void* d_out, int out_size) {
    const float* x = (const float*)d_in[0];
    const float* a = (const float*)d_in[1];
    // Defensive input-order check: a has exactly F=64 elements.
    if (n_in >= 2 && in_sizes[0] == F_DIM) {
        x = (const float*)d_in[1];
        a = (const float*)d_in[0];
    }
    float* out = (float*)d_out;

    const int smem_bytes = V_DIM * F_DIM * (int)sizeof(float);  // 51200 > 48K
    cudaFuncSetAttribute(k_compute, cudaFuncAttributeMaxDynamicSharedMemorySize,
                         smem_bytes);

    dim3 g1(N_DIM, N_DIM * T_DIM);   // (4, 48)
    k_compute<<<g1, 256, smem_bytes>>>(x, a, out);

    dim3 g2(N_DIM * T_DIM, 4);       // (48, 4)
    k_norm<<<g2, 256>>>(out);
}